// round 15
// baseline (speedup 1.0000x reference)
#include <cuda_runtime.h>
#include <cuda_fp16.h>
#include <cstdint>

// ---------------------------------------------------------------------------
// SoftPatternClassifier on GB300 — vocab+column-compacted 3xFP16 GEMM
//   R15: persistent GEMM (atomic tile counter, 296 CTAs) with 128v x 64c
//        tiles — eliminates wave quantization (440 tiles / 296 slots was
//        costing ~1.34x on an issue-floor-bound kernel).
// ---------------------------------------------------------------------------

#define BDIM 64
#define LDIM 512
#define VDIM 20000
#define PDIM 150
#define CDIM 600              // compacted transition columns
#define KDIM 300
#define NEGF (-1000000000.0f)

#define TSTR 640              // table row stride (= CPAD)
#define KPAD 304              // 19 chunks of 16
#define NPAIR (KPAD / 2)      // 152 half2 pairs per row
#define CPAD 640              // 10 * 64
#define VPAD 20096            // 157 * 128

#define TK 16
#define NCHUNK (KPAD / TK)    // 19
#define NCT 10                // c-tiles of 64

#define NSC 16                // scan time-chunks
#define SCT 32                // positions per scan chunk

// __device__ scratch (allocation-free rule)
__device__ float d_table[(size_t)VPAD * TSTR];   // ~51 MB (cid-indexed)
__device__ uint2 d_Ac[CPAD * NPAIR];             // (hi2, lo2) packed, c rows
__device__ uint2 d_Bc[(size_t)VPAD * NPAIR];     // (hi2, lo2) packed, token rows
__device__ float d_part[BDIM][NSC][160];
__device__ int   d_flag[VDIM];
__device__ int   d_cid[VDIM];
__device__ int   d_used[VPAD];
__device__ int   d_count;
__device__ int   d_tile;

// ---------------------------------------------------------------------------
// helpers
// ---------------------------------------------------------------------------
__device__ __forceinline__ float logsig(float x) {
    return fminf(x, 0.0f) - log1pf(expf(-fabsf(x)));
}
// compact col c' -> diags/bias row (p*6 + m)
__device__ __forceinline__ int colmap(int c) {
    if (c < 150) { int p = c / 3;  int m = c - 3 * p;          return p * 6 + m; }
    if (c < 350) { int q = c - 150; int p = q >> 2; int m = q & 3;  return (50 + p) * 6 + m; }
    int q = c - 350; int p = q / 5; int m = q - 5 * p;         return (100 + p) * 6 + m;
}
__device__ __forceinline__ void cpa16(uint32_t dst, const void* src) {
    asm volatile("cp.async.cg.shared.global [%0], [%1], 16;" :: "r"(dst), "l"(src) : "memory");
}
#define CPA_COMMIT() asm volatile("cp.async.commit_group;" ::: "memory")
#define CPA_WAIT1()  asm volatile("cp.async.wait_group 1;" ::: "memory")
#define CPA_WAIT0()  asm volatile("cp.async.wait_group 0;" ::: "memory")

__device__ __forceinline__ uint32_t smem_u32(const void* p) {
    uint32_t a;
    asm("{ .reg .u64 t; cvta.to.shared.u64 t, %1; cvt.u32.u64 %0, t; }" : "=r"(a) : "l"(p));
    return a;
}

// pair-interleave within groups of 8 pairs: stored order (0,4,1,5,2,6,3,7)
__device__ __forceinline__ int pslot(int j) {
    return (j & ~7) + 2 * (j & 3) + ((j >> 2) & 1);
}

__device__ __forceinline__ void mma16816(float* d, uint32_t a0, uint32_t a1,
                                         uint32_t a2, uint32_t a3,
                                         uint32_t b0, uint32_t b1) {
    asm volatile(
        "mma.sync.aligned.m16n8k16.row.col.f32.f16.f16.f32 "
        "{%0,%1,%2,%3}, {%4,%5,%6,%7}, {%8,%9}, {%0,%1,%2,%3};"
        : "+f"(d[0]), "+f"(d[1]), "+f"(d[2]), "+f"(d[3])
        : "r"(a0), "r"(a1), "r"(a2), "r"(a3), "r"(b0), "r"(b1));
}

__device__ __forceinline__ uint2 fp16pack(float x0, float x1) {
    __half h0 = __float2half_rn(x0);
    __half h1 = __float2half_rn(x1);
    __half l0 = __float2half_rn(x0 - __half2float(h0));
    __half l1 = __float2half_rn(x1 - __half2float(h1));
    __half2 hh = __halves2half2(h0, h1);
    __half2 ll = __halves2half2(l0, l1);
    uint2 r;
    r.x = *reinterpret_cast<uint32_t*>(&hh);
    r.y = *reinterpret_cast<uint32_t*>(&ll);
    return r;
}

// ---------------------------------------------------------------------------
// A. fused: split_diags (blocks [0,380)) + clear (blocks [380,459))
// ---------------------------------------------------------------------------
#define SD_BLOCKS ((CPAD * NPAIR + 255) / 256)         // 380
#define CL_BLOCKS ((VPAD + 255) / 256)                 // 79

__global__ void prepA_kernel(const float* __restrict__ diags) {
    if (blockIdx.x >= SD_BLOCKS) {
        int i = (blockIdx.x - SD_BLOCKS) * blockDim.x + threadIdx.x;
        if (i < VDIM) { d_flag[i] = 0; d_cid[i] = 0; }
        if (i < VPAD) d_used[i] = 0;
        if (i == 0) { d_count = 0; d_tile = 0; }
        return;
    }
    int i = blockIdx.x * blockDim.x + threadIdx.x;
    if (i >= CPAD * NPAIR) return;
    int c = i / NPAIR;
    int j = i - c * NPAIR;
    int k0 = 2 * j, k1 = 2 * j + 1;
    float x0 = 0.0f, x1 = 0.0f;
    if (c < CDIM) {
        int row = colmap(c);
        if (k0 < KDIM) x0 = diags[row * KDIM + k0];
        if (k1 < KDIM) x1 = diags[row * KDIM + k1];
    }
    d_Ac[c * NPAIR + pslot(j)] = fp16pack(x0, x1);
}

// ---------------------------------------------------------------------------
// B. mark tokens appearing within doc_lens
// ---------------------------------------------------------------------------
__global__ void mark_kernel(const int* __restrict__ docs,
                            const int* __restrict__ doc_lens) {
    int i = blockIdx.x * blockDim.x + threadIdx.x;
    int b = i >> 9, t = i & (LDIM - 1);
    if (b < BDIM && t < doc_lens[b]) d_flag[docs[i]] = 1;
}

// ---------------------------------------------------------------------------
// C. fused: split_emb (y in [0,10)) + assign (y == 10, x < 79)
// ---------------------------------------------------------------------------
__global__ void prepC_kernel(const float* __restrict__ E) {
    int tx = threadIdx.x, ty = threadIdx.y;   // (32, 8)
    int tid = ty * 32 + tx;

    if (blockIdx.y == (KPAD + 31) / 32) {     // assign row
        if (blockIdx.x >= CL_BLOCKS) return;
        int v = blockIdx.x * 256 + tid;
        if (v >= VDIM) return;
        int lane = tx;
        int f = d_flag[v];
        unsigned mask = __ballot_sync(0xffffffffu, f != 0);
        int base = 0;
        if (lane == 0 && mask) base = atomicAdd(&d_count, __popc(mask));
        base = __shfl_sync(0xffffffffu, base, 0);
        if (f) {
            int cid = base + __popc(mask & ((1u << lane) - 1));
            d_cid[v] = cid;
            d_used[cid] = v;
        }
        return;
    }

    __shared__ float tile[32][33];
    int vt = blockIdx.x * 32;
    int kt = blockIdx.y * 32;
#pragma unroll
    for (int r = 0; r < 4; r++) {
        int k = kt + ty + r * 8, v = vt + tx;
        tile[ty + r * 8][tx] = (k < KDIM && v < VDIM) ? E[(size_t)k * VDIM + v] : 0.0f;
    }
    __syncthreads();
#pragma unroll
    for (int w = 0; w < 2; w++) {
        int idx = tid + 256 * w;               // 0..511 = 32 v x 16 pairs
        int j = idx & 15, vv = idx >> 4;
        int gp = (kt >> 1) + j;
        if (gp >= NPAIR) continue;
        int v = vt + vv;
        if (v >= VDIM || !d_flag[v]) continue;
        d_Bc[(size_t)v * NPAIR + pslot(gp)] =
            fp16pack(tile[2 * j][vv], tile[2 * j + 1][vv]);
    }
}

// ---------------------------------------------------------------------------
// D. persistent GEMM: tiles of 128 cid x 64 c', atomic tile counter.
// ---------------------------------------------------------------------------
#define ROW_BYTES   64                         // 8 uint2 per row per chunk
#define A_BYTES     (128 * ROW_BYTES)          // 8192
#define B_BYTES     (64 * ROW_BYTES)           // 4096
#define STAGE_BYTES (A_BYTES + B_BYTES)        // 12288
#define OFF_A 0
#define OFF_B A_BYTES
#define TOK_BYTES   512
#define GSMEM_TOTAL (2 * STAGE_BYTES + TOK_BYTES + 16)  // 25104

__global__ void __launch_bounds__(256, 2)
gemm_mma_kernel(const float* __restrict__ bias) {
    extern __shared__ __align__(16) char smem[];
    const uint32_t sb = smem_u32(smem);
    int* s_tok  = (int*)(smem + 2 * STAGE_BYTES);
    int* s_tile = (int*)(smem + 2 * STAGE_BYTES + TOK_BYTES);

    const int cnt    = d_count;
    const int nV     = (cnt + 127) >> 7;
    const int nTiles = nV * NCT;

    const int tid = threadIdx.x;
    const int wid = tid >> 5;
    const int lid = tid & 31;
    const int g   = lid >> 2;
    const int t   = lid & 3;
    const int wm  = (wid & 3) * 32;
    const int wn  = (wid >> 2) * 32;           // 2 n-warps x 32 c

    for (;;) {
        if (tid == 0) *s_tile = atomicAdd(&d_tile, 1);
        __syncthreads();
        const int tile = *s_tile;
        if (tile >= nTiles) break;
        const int vt = tile / NCT;
        const int ct = tile - vt * NCT;
        const int vBase = vt * 128;
        const int cBase = ct * 64;

        if (tid < 128) {
            int cid = vBase + tid;
            s_tok[tid] = d_used[(cid < cnt) ? cid : 0];
        }
        __syncthreads();

        const uint2* gAc = d_Ac + (size_t)cBase * NPAIR;

        auto load_chunk = [&](int kc, int s) {
            const uint32_t st = sb + s * STAGE_BYTES;
            const int p0 = kc * 8;
            // A (cid rows): 128 rows x 64B, 2x cp.async per thread
            {
                int r = tid >> 1, h = tid & 1;
                uint32_t so = (uint32_t)r * ROW_BYTES + h * 32;
                size_t gm = (size_t)s_tok[r] * NPAIR + p0 + h * 4;
                cpa16(st + OFF_A + so,      d_Bc + gm);
                cpa16(st + OFF_A + so + 16, d_Bc + gm + 2);
            }
            // B (c rows): 64 rows x 64B, 1x cp.async per thread
            {
                int r = tid >> 2, h = tid & 3;
                uint32_t so = (uint32_t)r * ROW_BYTES + h * 16;
                size_t gn = (size_t)r * NPAIR + p0 + h * 2;
                cpa16(st + OFF_B + so, gAc + gn);
            }
            CPA_COMMIT();
        };

        float acc[2][4][4];
#pragma unroll
        for (int mi = 0; mi < 2; mi++)
#pragma unroll
            for (int ni = 0; ni < 4; ni++)
#pragma unroll
                for (int e = 0; e < 4; e++) acc[mi][ni][e] = 0.0f;

        load_chunk(0, 0);
        load_chunk(1, 1);

        for (int i = 0; i < NCHUNK; i++) {
            const int s = i & 1;
            if (i + 1 < NCHUNK) { CPA_WAIT1(); } else { CPA_WAIT0(); }
            __syncthreads();

            const char* stg = smem + s * STAGE_BYTES;

            uint32_t Ah[2][4], Al[2][4];
#pragma unroll
            for (int mi = 0; mi < 2; mi++) {
                int r0 = wm + mi * 16 + g;
                float4 f0 = *(const float4*)(stg + OFF_A + r0 * ROW_BYTES + t * 16);
                float4 f1 = *(const float4*)(stg + OFF_A + (r0 + 8) * ROW_BYTES + t * 16);
                Ah[mi][0] = __float_as_uint(f0.x); Al[mi][0] = __float_as_uint(f0.y);
                Ah[mi][2] = __float_as_uint(f0.z); Al[mi][2] = __float_as_uint(f0.w);
                Ah[mi][1] = __float_as_uint(f1.x); Al[mi][1] = __float_as_uint(f1.y);
                Ah[mi][3] = __float_as_uint(f1.z); Al[mi][3] = __float_as_uint(f1.w);
            }
#pragma unroll
            for (int ni = 0; ni < 4; ni++) {
                int rn = wn + ni * 8 + g;
                float4 fb = *(const float4*)(stg + OFF_B + rn * ROW_BYTES + t * 16);
                uint32_t bh0 = __float_as_uint(fb.x), bl0 = __float_as_uint(fb.y);
                uint32_t bh1 = __float_as_uint(fb.z), bl1 = __float_as_uint(fb.w);
#pragma unroll
                for (int mi = 0; mi < 2; mi++) {
                    mma16816(acc[mi][ni], Ah[mi][0], Ah[mi][1], Ah[mi][2], Ah[mi][3], bh0, bh1);
                    mma16816(acc[mi][ni], Ah[mi][0], Ah[mi][1], Ah[mi][2], Ah[mi][3], bl0, bl1);
                    mma16816(acc[mi][ni], Al[mi][0], Al[mi][1], Al[mi][2], Al[mi][3], bh0, bh1);
                }
            }
            __syncthreads();
            if (i + 2 < NCHUNK) load_chunk(i + 2, s);
        }

        // ---- epilogue: +bias, logsig, float2 stores to table[cid][c'] ----
#pragma unroll
        for (int ni = 0; ni < 4; ni++) {
            const int c = cBase + wn + ni * 8 + 2 * t;
            if (c >= CDIM) continue;
            const int c1 = c + 1;
            const float b0 = __ldg(&bias[colmap(c)]);
            const float b1 = (c1 < CDIM) ? __ldg(&bias[colmap(c1)]) : 0.0f;
#pragma unroll
            for (int mi = 0; mi < 2; mi++) {
                const int v0 = vBase + wm + mi * 16 + g;
                const int v1 = v0 + 8;
                if (v0 < cnt) {
                    float2 r;
                    r.x = logsig(acc[mi][ni][0] + b0);
                    r.y = logsig(acc[mi][ni][1] + b1);
                    *(float2*)&d_table[(size_t)v0 * TSTR + c] = r;
                }
                if (v1 < cnt) {
                    float2 r;
                    r.x = logsig(acc[mi][ni][2] + b0);
                    r.y = logsig(acc[mi][ni][3] + b1);
                    *(float2*)&d_table[(size_t)v1 * TSTR + c] = r;
                }
            }
        }
    }
}

// ---------------------------------------------------------------------------
// E. scan: block (b, q) handles chunks ch=2q and 2q+1, interleaved per
//    thread (2 independent chains). Uniform 36-step loop.
// ---------------------------------------------------------------------------
#define NTS 36

__global__ void __launch_bounds__(160)
scan_part_kernel(const int*   __restrict__ docs,
                 const int*   __restrict__ doc_lens,
                 const float* __restrict__ wildcards) {
    const int b   = blockIdx.x;
    const int q   = blockIdx.y;
    const int tid = threadIdx.x;
    const int p   = tid;
    const bool valid = (p < PDIM);

    const int ch0 = 2 * q, ch1 = 2 * q + 1;
    const int len = doc_lens[b];
    const int c00 = ch0 * SCT, c01 = ch1 * SCT;

    if (len <= c00) {
        if (valid) { d_part[b][ch0][p] = NEGF; d_part[b][ch1][p] = NEGF; }
        return;
    }

    const int ts0 = (c00 >= 4) ? c00 - 4 : 0;
    const int ts1 = c01 - 4;

    __shared__ int tok[2][NTS];
    for (int i = tid; i < 2 * NTS; i += 160) {
        int j = i / NTS, ii = i - j * NTS;
        int ts = j ? ts1 : ts0;
        int gi = ts + ii; if (gi >= LDIM) gi = LDIM - 1;
        tok[j][ii] = d_cid[docs[b * LDIM + gi]];
    }
    __syncthreads();

    const int endSel = p / 50;
    const int off    = (endSel == 0) ? 3 * p
                     : (endSel == 1) ? 4 * p - 50
                                     : 5 * p - 150;

    float wl[5];
#pragma unroll
    for (int m = 0; m < 5; m++)
        wl[m] = valid ? logsig(__ldg(&wildcards[p * 5 + m])) : 0.0f;

    float ha[2][5], sc[2];
    float pf[2][4][5];
#pragma unroll
    for (int j = 0; j < 2; j++) {
        sc[j] = NEGF;
#pragma unroll
        for (int m = 0; m < 5; m++) ha[j][m] = NEGF;
#pragma unroll
        for (int u = 0; u < 4; u++) {
            if (valid) {
                const float* row = &d_table[(size_t)tok[j][u] * TSTR + off];
#pragma unroll
                for (int m = 0; m < 5; m++) pf[j][u][m] = __ldg(&row[m]);
            } else {
#pragma unroll
                for (int m = 0; m < 5; m++) pf[j][u][m] = 0.0f;
            }
        }
    }

    const int lo0 = c00 - ts0;
    const int hi0 = (len < c00 + SCT ? len : c00 + SCT) - ts0;
    const int lo1 = 4;
    const int hi1 = (len < c01 + SCT ? len : c01 + SCT) - ts1;

    for (int i = 0; i < NTS; i += 4) {
#pragma unroll
        for (int u = 0; u < 4; u++) {
            const int li = i + u;
            const int ni = li + 4;
#pragma unroll
            for (int j = 0; j < 2; j++) {
                float e0 = fmaxf(pf[j][u][0], wl[0]);
                float e1 = fmaxf(pf[j][u][1], wl[1]);
                float e2 = fmaxf(pf[j][u][2], wl[2]);
                float e3 = fmaxf(pf[j][u][3], wl[3]);
                float e4 = fmaxf(pf[j][u][4], wl[4]);
                ha[j][4] = ha[j][3] + e4;
                ha[j][3] = ha[j][2] + e3;
                ha[j][2] = ha[j][1] + e2;
                ha[j][1] = ha[j][0] + e1;
                ha[j][0] = e0;
                float ev = (endSel == 0) ? ha[j][2]
                         : (endSel == 1) ? ha[j][3] : ha[j][4];
                const int lo = j ? lo1 : lo0;
                const int hi = j ? hi1 : hi0;
                sc[j] = (li >= lo && li < hi) ? fmaxf(sc[j], ev) : sc[j];
                if (ni < NTS && valid) {
                    const float* row = &d_table[(size_t)tok[j][ni] * TSTR + off];
#pragma unroll
                    for (int m = 0; m < 5; m++) pf[j][u][m] = __ldg(&row[m]);
                }
            }
        }
    }

    if (valid) {
        d_part[b][ch0][p] = sc[0];
        d_part[b][ch1][p] = sc[1];
    }
}

// ---------------------------------------------------------------------------
// F. final: reduce chunks, exp/LN/heaviside/linear
// ---------------------------------------------------------------------------
__global__ void __launch_bounds__(160)
scan_final_kernel(const float* __restrict__ gamma,
                  const float* __restrict__ beta,
                  const float* __restrict__ W,
                  const float* __restrict__ lb,
                  float*       __restrict__ out) {
    const int b   = blockIdx.x;
    const int tid = threadIdx.x;
    const bool valid = (tid < PDIM);

    __shared__ float sh[192];
    __shared__ float sred[2];

    float sc = NEGF;
    if (valid) {
#pragma unroll
        for (int ch = 0; ch < NSC; ch++) sc = fmaxf(sc, d_part[b][ch][tid]);
    }
    float score = valid ? expf(sc) : 0.0f;

    sh[tid] = score;
    __syncthreads();
    if (tid < 32) {
        float s = 0.0f;
        for (int i = tid; i < PDIM; i += 32) s += sh[i];
#pragma unroll
        for (int o = 16; o > 0; o >>= 1) s += __shfl_down_sync(0xffffffffu, s, o);
        if (tid == 0) sred[0] = s * (1.0f / PDIM);
    }
    __syncthreads();
    const float mu = sred[0];

    float d = score - mu;
    sh[tid] = valid ? d * d : 0.0f;
    __syncthreads();
    if (tid < 32) {
        float s = 0.0f;
        for (int i = tid; i < PDIM; i += 32) s += sh[i];
#pragma unroll
        for (int o = 16; o > 0; o >>= 1) s += __shfl_down_sync(0xffffffffu, s, o);
        if (tid == 0) sred[1] = s * (1.0f / PDIM);
    }
    __syncthreads();
    const float var = sred[1];

    float bin = 0.0f;
    if (valid) {
        float norm = (score - mu) * rsqrtf(var + 1e-5f) * __ldg(&gamma[tid]) + __ldg(&beta[tid]);
        bin = (norm > 0.0f) ? 1.0f : 0.0f;
    }

    sh[tid] = valid ? bin * __ldg(&W[tid]) : 0.0f;
    __syncthreads();
    if (tid < 32) {
        float s = 0.0f;
        for (int i = tid; i < PDIM; i += 32) s += sh[i];
#pragma unroll
        for (int o = 16; o > 0; o >>= 1) s += __shfl_down_sync(0xffffffffu, s, o);
        if (tid == 0) out[b * 2 + 0] = s + __ldg(&lb[0]);
    }
    __syncthreads();
    sh[tid] = valid ? bin * __ldg(&W[PDIM + tid]) : 0.0f;
    __syncthreads();
    if (tid < 32) {
        float s = 0.0f;
        for (int i = tid; i < PDIM; i += 32) s += sh[i];
#pragma unroll
        for (int o = 16; o > 0; o >>= 1) s += __shfl_down_sync(0xffffffffu, s, o);
        if (tid == 0) out[b * 2 + 1] = s + __ldg(&lb[1]);
    }
}

// ---------------------------------------------------------------------------
// launch
// ---------------------------------------------------------------------------
extern "C" void kernel_launch(void* const* d_in, const int* in_sizes, int n_in,
                              void* d_out, int out_size) {
    const int*   docs      = (const int*)  d_in[0];
    const int*   doc_lens  = (const int*)  d_in[1];
    const float* emb       = (const float*)d_in[2];
    const float* diags     = (const float*)d_in[3];
    const float* bias      = (const float*)d_in[4];
    const float* wildcards = (const float*)d_in[5];
    const float* ln_gamma  = (const float*)d_in[6];
    const float* ln_beta   = (const float*)d_in[7];
    const float* linear_w  = (const float*)d_in[8];
    const float* linear_b  = (const float*)d_in[9];
    float*       out       = (float*)d_out;

    (void)in_sizes; (void)n_in; (void)out_size;

    cudaFuncSetAttribute(gemm_mma_kernel,
                         cudaFuncAttributeMaxDynamicSharedMemorySize, GSMEM_TOTAL);

    prepA_kernel<<<SD_BLOCKS + CL_BLOCKS, 256>>>(diags);
    mark_kernel<<<(BDIM * LDIM + 255) / 256, 256>>>(docs, doc_lens);

    dim3 cgrid((VPAD + 31) / 32, (KPAD + 31) / 32 + 1);   // (628, 11)
    prepC_kernel<<<cgrid, dim3(32, 8)>>>(emb);

    gemm_mma_kernel<<<296, 256, GSMEM_TOTAL>>>(bias);     // persistent

    dim3 sgrid(BDIM, NSC / 2);                            // (64, 8)
    scan_part_kernel<<<sgrid, 160>>>(docs, doc_lens, wildcards);

    scan_final_kernel<<<BDIM, 160>>>(ln_gamma, ln_beta, linear_w, linear_b, out);
}

// round 16
// speedup vs baseline: 1.0775x; 1.0775x over previous
#include <cuda_runtime.h>
#include <cuda_fp16.h>
#include <cstdint>

// ---------------------------------------------------------------------------
// SoftPatternClassifier on GB300 — vocab+column-compacted 3xFP16 GEMM
//   R16: GEMM tiles 64v x 128c (880 tiles) — halves tile granularity along V
//        to kill the 1.35x 2-CTA-residency makespan stretch (R15's 64c split
//        doubled A traffic; V-split keeps gather traffic constant).
// ---------------------------------------------------------------------------

#define BDIM 64
#define LDIM 512
#define VDIM 20000
#define PDIM 150
#define CDIM 600              // compacted transition columns
#define KDIM 300
#define NEGF (-1000000000.0f)

#define TSTR 640              // table row stride (= CPAD)
#define KPAD 304              // 19 chunks of 16
#define NPAIR (KPAD / 2)      // 152 half2 pairs per row
#define CPAD 640              // 5 * 128
#define VPAD 20096            // 157 * 128

#define TK 16
#define NCHUNK (KPAD / TK)    // 19

#define NSC 16                // scan time-chunks
#define SCT 32                // positions per scan chunk

// __device__ scratch (allocation-free rule)
__device__ float d_table[(size_t)VPAD * TSTR];   // ~51 MB (cid-indexed)
__device__ uint2 d_Ac[CPAD * NPAIR];             // (hi2, lo2) packed, c rows
__device__ uint2 d_Bc[(size_t)VPAD * NPAIR];     // (hi2, lo2) packed, token rows
__device__ float d_part[BDIM][NSC][160];
__device__ int   d_flag[VDIM];
__device__ int   d_cid[VDIM];
__device__ int   d_used[VPAD];
__device__ int   d_count;

// ---------------------------------------------------------------------------
// helpers
// ---------------------------------------------------------------------------
__device__ __forceinline__ float logsig(float x) {
    return fminf(x, 0.0f) - log1pf(expf(-fabsf(x)));
}
// compact col c' -> diags/bias row (p*6 + m)
__device__ __forceinline__ int colmap(int c) {
    if (c < 150) { int p = c / 3;  int m = c - 3 * p;          return p * 6 + m; }
    if (c < 350) { int q = c - 150; int p = q >> 2; int m = q & 3;  return (50 + p) * 6 + m; }
    int q = c - 350; int p = q / 5; int m = q - 5 * p;         return (100 + p) * 6 + m;
}
__device__ __forceinline__ void cpa16(uint32_t dst, const void* src) {
    asm volatile("cp.async.cg.shared.global [%0], [%1], 16;" :: "r"(dst), "l"(src) : "memory");
}
#define CPA_COMMIT() asm volatile("cp.async.commit_group;" ::: "memory")
#define CPA_WAIT1()  asm volatile("cp.async.wait_group 1;" ::: "memory")
#define CPA_WAIT0()  asm volatile("cp.async.wait_group 0;" ::: "memory")

__device__ __forceinline__ uint32_t smem_u32(const void* p) {
    uint32_t a;
    asm("{ .reg .u64 t; cvta.to.shared.u64 t, %1; cvt.u32.u64 %0, t; }" : "=r"(a) : "l"(p));
    return a;
}

// pair-interleave within groups of 8 pairs: stored order (0,4,1,5,2,6,3,7)
__device__ __forceinline__ int pslot(int j) {
    return (j & ~7) + 2 * (j & 3) + ((j >> 2) & 1);
}

__device__ __forceinline__ void mma16816(float* d, uint32_t a0, uint32_t a1,
                                         uint32_t a2, uint32_t a3,
                                         uint32_t b0, uint32_t b1) {
    asm volatile(
        "mma.sync.aligned.m16n8k16.row.col.f32.f16.f16.f32 "
        "{%0,%1,%2,%3}, {%4,%5,%6,%7}, {%8,%9}, {%0,%1,%2,%3};"
        : "+f"(d[0]), "+f"(d[1]), "+f"(d[2]), "+f"(d[3])
        : "r"(a0), "r"(a1), "r"(a2), "r"(a3), "r"(b0), "r"(b1));
}

__device__ __forceinline__ uint2 fp16pack(float x0, float x1) {
    __half h0 = __float2half_rn(x0);
    __half h1 = __float2half_rn(x1);
    __half l0 = __float2half_rn(x0 - __half2float(h0));
    __half l1 = __float2half_rn(x1 - __half2float(h1));
    __half2 hh = __halves2half2(h0, h1);
    __half2 ll = __halves2half2(l0, l1);
    uint2 r;
    r.x = *reinterpret_cast<uint32_t*>(&hh);
    r.y = *reinterpret_cast<uint32_t*>(&ll);
    return r;
}

// ---------------------------------------------------------------------------
// A. fused: split_diags (blocks [0,380)) + clear (blocks [380,459))
// ---------------------------------------------------------------------------
#define SD_BLOCKS ((CPAD * NPAIR + 255) / 256)         // 380
#define CL_BLOCKS ((VPAD + 255) / 256)                 // 79

__global__ void prepA_kernel(const float* __restrict__ diags) {
    if (blockIdx.x >= SD_BLOCKS) {
        int i = (blockIdx.x - SD_BLOCKS) * blockDim.x + threadIdx.x;
        if (i < VDIM) { d_flag[i] = 0; d_cid[i] = 0; }
        if (i < VPAD) d_used[i] = 0;
        if (i == 0) d_count = 0;
        return;
    }
    int i = blockIdx.x * blockDim.x + threadIdx.x;
    if (i >= CPAD * NPAIR) return;
    int c = i / NPAIR;
    int j = i - c * NPAIR;
    int k0 = 2 * j, k1 = 2 * j + 1;
    float x0 = 0.0f, x1 = 0.0f;
    if (c < CDIM) {
        int row = colmap(c);
        if (k0 < KDIM) x0 = diags[row * KDIM + k0];
        if (k1 < KDIM) x1 = diags[row * KDIM + k1];
    }
    d_Ac[c * NPAIR + pslot(j)] = fp16pack(x0, x1);
}

// ---------------------------------------------------------------------------
// B. mark tokens appearing within doc_lens
// ---------------------------------------------------------------------------
__global__ void mark_kernel(const int* __restrict__ docs,
                            const int* __restrict__ doc_lens) {
    int i = blockIdx.x * blockDim.x + threadIdx.x;
    int b = i >> 9, t = i & (LDIM - 1);
    if (b < BDIM && t < doc_lens[b]) d_flag[docs[i]] = 1;
}

// ---------------------------------------------------------------------------
// C. fused: split_emb (y in [0,10)) + assign (y == 10, x < 79)
// ---------------------------------------------------------------------------
__global__ void prepC_kernel(const float* __restrict__ E) {
    int tx = threadIdx.x, ty = threadIdx.y;   // (32, 8)
    int tid = ty * 32 + tx;

    if (blockIdx.y == (KPAD + 31) / 32) {     // assign row
        if (blockIdx.x >= CL_BLOCKS) return;
        int v = blockIdx.x * 256 + tid;
        if (v >= VDIM) return;
        int lane = tx;
        int f = d_flag[v];
        unsigned mask = __ballot_sync(0xffffffffu, f != 0);
        int base = 0;
        if (lane == 0 && mask) base = atomicAdd(&d_count, __popc(mask));
        base = __shfl_sync(0xffffffffu, base, 0);
        if (f) {
            int cid = base + __popc(mask & ((1u << lane) - 1));
            d_cid[v] = cid;
            d_used[cid] = v;
        }
        return;
    }

    __shared__ float tile[32][33];
    int vt = blockIdx.x * 32;
    int kt = blockIdx.y * 32;
#pragma unroll
    for (int r = 0; r < 4; r++) {
        int k = kt + ty + r * 8, v = vt + tx;
        tile[ty + r * 8][tx] = (k < KDIM && v < VDIM) ? E[(size_t)k * VDIM + v] : 0.0f;
    }
    __syncthreads();
#pragma unroll
    for (int w = 0; w < 2; w++) {
        int idx = tid + 256 * w;               // 0..511 = 32 v x 16 pairs
        int j = idx & 15, vv = idx >> 4;
        int gp = (kt >> 1) + j;
        if (gp >= NPAIR) continue;
        int v = vt + vv;
        if (v >= VDIM || !d_flag[v]) continue;
        d_Bc[(size_t)v * NPAIR + pslot(gp)] =
            fp16pack(tile[2 * j][vv], tile[2 * j + 1][vv]);
    }
}

// ---------------------------------------------------------------------------
// D. GEMM over USED tokens only: D[64 cid x 128 c'] per CTA (880 tiles).
//    8 warps: 4(m) x 2(n), warp = 16v x 64c. 11 LDS.128 / chunk / warp.
// ---------------------------------------------------------------------------
#define ROW_BYTES   64                         // 8 uint2 per row per chunk
#define A_BYTES     (64 * ROW_BYTES)           // 4096  (cid rows)
#define B_BYTES     (128 * ROW_BYTES)          // 8192  (c rows)
#define STAGE_BYTES (A_BYTES + B_BYTES)        // 12288
#define OFF_A 0
#define OFF_B A_BYTES
#define TOK_BYTES   256
#define GSMEM_TOTAL (2 * STAGE_BYTES + TOK_BYTES)  // 24832

__global__ void __launch_bounds__(256, 2)
gemm_mma_kernel(const float* __restrict__ bias) {
    extern __shared__ __align__(16) char smem[];
    const uint32_t sb = smem_u32(smem);
    int* s_tok = (int*)(smem + 2 * STAGE_BYTES);

    const int cnt = d_count;
    const int vBase = blockIdx.x * 64;         // compact-id base
    if (vBase >= cnt) return;

    const int tid = threadIdx.x;
    const int wid = tid >> 5;
    const int lid = tid & 31;
    const int g   = lid >> 2;
    const int t   = lid & 3;
    const int wm  = (wid & 3) * 16;            // 4 m-warps x 16 v
    const int wn  = (wid >> 2) * 64;           // 2 n-warps x 64 c
    const int cBase = blockIdx.y * 128;

    if (tid < 64) {
        int cid = vBase + tid;
        s_tok[tid] = d_used[(cid < cnt) ? cid : 0];
    }
    __syncthreads();

    const uint2* gAc = d_Ac + (size_t)cBase * NPAIR;

    auto load_chunk = [&](int kc, int s) {
        const uint32_t st = sb + s * STAGE_BYTES;
        const int p0 = kc * 8;
        // A (cid rows): 64 rows x 64B -> 256 x 16B, 1 per thread
        {
            int r = tid >> 2, h = tid & 3;
            uint32_t so = (uint32_t)r * ROW_BYTES + h * 16;
            size_t gm = (size_t)s_tok[r] * NPAIR + p0 + h * 2;
            cpa16(st + OFF_A + so, d_Bc + gm);
        }
        // B (c rows): 128 rows x 64B -> 512 x 16B, 2 per thread
        {
            int r = tid >> 1, h = tid & 1;
            uint32_t so = (uint32_t)r * ROW_BYTES + h * 32;
            size_t gn = (size_t)r * NPAIR + p0 + h * 4;
            cpa16(st + OFF_B + so,      gAc + gn);
            cpa16(st + OFF_B + so + 16, gAc + gn + 2);
        }
        CPA_COMMIT();
    };

    float acc[8][4];
#pragma unroll
    for (int ni = 0; ni < 8; ni++)
#pragma unroll
        for (int e = 0; e < 4; e++) acc[ni][e] = 0.0f;

    load_chunk(0, 0);
    load_chunk(1, 1);

    for (int i = 0; i < NCHUNK; i++) {
        const int s = i & 1;
        if (i + 1 < NCHUNK) { CPA_WAIT1(); } else { CPA_WAIT0(); }
        __syncthreads();

        const char* stg = smem + s * STAGE_BYTES;

        uint32_t Ah[4], Al[4];
        {
            int r0 = wm + g;
            float4 f0 = *(const float4*)(stg + OFF_A + r0 * ROW_BYTES + t * 16);
            float4 f1 = *(const float4*)(stg + OFF_A + (r0 + 8) * ROW_BYTES + t * 16);
            Ah[0] = __float_as_uint(f0.x); Al[0] = __float_as_uint(f0.y);
            Ah[2] = __float_as_uint(f0.z); Al[2] = __float_as_uint(f0.w);
            Ah[1] = __float_as_uint(f1.x); Al[1] = __float_as_uint(f1.y);
            Ah[3] = __float_as_uint(f1.z); Al[3] = __float_as_uint(f1.w);
        }
#pragma unroll
        for (int ni = 0; ni < 8; ni++) {
            int rn = wn + ni * 8 + g;
            float4 fb = *(const float4*)(stg + OFF_B + rn * ROW_BYTES + t * 16);
            uint32_t bh0 = __float_as_uint(fb.x), bl0 = __float_as_uint(fb.y);
            uint32_t bh1 = __float_as_uint(fb.z), bl1 = __float_as_uint(fb.w);
            mma16816(acc[ni], Ah[0], Ah[1], Ah[2], Ah[3], bh0, bh1);
            mma16816(acc[ni], Ah[0], Ah[1], Ah[2], Ah[3], bl0, bl1);
            mma16816(acc[ni], Al[0], Al[1], Al[2], Al[3], bh0, bh1);
        }
        __syncthreads();
        if (i + 2 < NCHUNK) load_chunk(i + 2, s);
    }

    // ---- epilogue: +bias, logsig, float2 stores to table[cid][c'] ----
#pragma unroll
    for (int ni = 0; ni < 8; ni++) {
        const int c = cBase + wn + ni * 8 + 2 * t;
        if (c >= CDIM) continue;
        const int c1 = c + 1;
        const float b0 = __ldg(&bias[colmap(c)]);
        const float b1 = (c1 < CDIM) ? __ldg(&bias[colmap(c1)]) : 0.0f;
        const int v0 = vBase + wm + g;
        const int v1 = v0 + 8;
        if (v0 < cnt) {
            float2 r;
            r.x = logsig(acc[ni][0] + b0);
            r.y = logsig(acc[ni][1] + b1);
            *(float2*)&d_table[(size_t)v0 * TSTR + c] = r;
        }
        if (v1 < cnt) {
            float2 r;
            r.x = logsig(acc[ni][2] + b0);
            r.y = logsig(acc[ni][3] + b1);
            *(float2*)&d_table[(size_t)v1 * TSTR + c] = r;
        }
    }
}

// ---------------------------------------------------------------------------
// E. scan: block (b, q) handles chunks ch=2q and 2q+1, interleaved per
//    thread (2 independent chains). Uniform 36-step loop.
// ---------------------------------------------------------------------------
#define NTS 36

__global__ void __launch_bounds__(160)
scan_part_kernel(const int*   __restrict__ docs,
                 const int*   __restrict__ doc_lens,
                 const float* __restrict__ wildcards) {
    const int b   = blockIdx.x;
    const int q   = blockIdx.y;
    const int tid = threadIdx.x;
    const int p   = tid;
    const bool valid = (p < PDIM);

    const int ch0 = 2 * q, ch1 = 2 * q + 1;
    const int len = doc_lens[b];
    const int c00 = ch0 * SCT, c01 = ch1 * SCT;

    if (len <= c00) {
        if (valid) { d_part[b][ch0][p] = NEGF; d_part[b][ch1][p] = NEGF; }
        return;
    }

    const int ts0 = (c00 >= 4) ? c00 - 4 : 0;
    const int ts1 = c01 - 4;

    __shared__ int tok[2][NTS];
    for (int i = tid; i < 2 * NTS; i += 160) {
        int j = i / NTS, ii = i - j * NTS;
        int ts = j ? ts1 : ts0;
        int gi = ts + ii; if (gi >= LDIM) gi = LDIM - 1;
        tok[j][ii] = d_cid[docs[b * LDIM + gi]];
    }
    __syncthreads();

    const int endSel = p / 50;
    const int off    = (endSel == 0) ? 3 * p
                     : (endSel == 1) ? 4 * p - 50
                                     : 5 * p - 150;

    float wl[5];
#pragma unroll
    for (int m = 0; m < 5; m++)
        wl[m] = valid ? logsig(__ldg(&wildcards[p * 5 + m])) : 0.0f;

    float ha[2][5], sc[2];
    float pf[2][4][5];
#pragma unroll
    for (int j = 0; j < 2; j++) {
        sc[j] = NEGF;
#pragma unroll
        for (int m = 0; m < 5; m++) ha[j][m] = NEGF;
#pragma unroll
        for (int u = 0; u < 4; u++) {
            if (valid) {
                const float* row = &d_table[(size_t)tok[j][u] * TSTR + off];
#pragma unroll
                for (int m = 0; m < 5; m++) pf[j][u][m] = __ldg(&row[m]);
            } else {
#pragma unroll
                for (int m = 0; m < 5; m++) pf[j][u][m] = 0.0f;
            }
        }
    }

    const int lo0 = c00 - ts0;
    const int hi0 = (len < c00 + SCT ? len : c00 + SCT) - ts0;
    const int lo1 = 4;
    const int hi1 = (len < c01 + SCT ? len : c01 + SCT) - ts1;

    for (int i = 0; i < NTS; i += 4) {
#pragma unroll
        for (int u = 0; u < 4; u++) {
            const int li = i + u;
            const int ni = li + 4;
#pragma unroll
            for (int j = 0; j < 2; j++) {
                float e0 = fmaxf(pf[j][u][0], wl[0]);
                float e1 = fmaxf(pf[j][u][1], wl[1]);
                float e2 = fmaxf(pf[j][u][2], wl[2]);
                float e3 = fmaxf(pf[j][u][3], wl[3]);
                float e4 = fmaxf(pf[j][u][4], wl[4]);
                ha[j][4] = ha[j][3] + e4;
                ha[j][3] = ha[j][2] + e3;
                ha[j][2] = ha[j][1] + e2;
                ha[j][1] = ha[j][0] + e1;
                ha[j][0] = e0;
                float ev = (endSel == 0) ? ha[j][2]
                         : (endSel == 1) ? ha[j][3] : ha[j][4];
                const int lo = j ? lo1 : lo0;
                const int hi = j ? hi1 : hi0;
                sc[j] = (li >= lo && li < hi) ? fmaxf(sc[j], ev) : sc[j];
                if (ni < NTS && valid) {
                    const float* row = &d_table[(size_t)tok[j][ni] * TSTR + off];
#pragma unroll
                    for (int m = 0; m < 5; m++) pf[j][u][m] = __ldg(&row[m]);
                }
            }
        }
    }

    if (valid) {
        d_part[b][ch0][p] = sc[0];
        d_part[b][ch1][p] = sc[1];
    }
}

// ---------------------------------------------------------------------------
// F. final: reduce chunks, exp/LN/heaviside/linear
// ---------------------------------------------------------------------------
__global__ void __launch_bounds__(160)
scan_final_kernel(const float* __restrict__ gamma,
                  const float* __restrict__ beta,
                  const float* __restrict__ W,
                  const float* __restrict__ lb,
                  float*       __restrict__ out) {
    const int b   = blockIdx.x;
    const int tid = threadIdx.x;
    const bool valid = (tid < PDIM);

    __shared__ float sh[192];
    __shared__ float sred[2];

    float sc = NEGF;
    if (valid) {
#pragma unroll
        for (int ch = 0; ch < NSC; ch++) sc = fmaxf(sc, d_part[b][ch][tid]);
    }
    float score = valid ? expf(sc) : 0.0f;

    sh[tid] = score;
    __syncthreads();
    if (tid < 32) {
        float s = 0.0f;
        for (int i = tid; i < PDIM; i += 32) s += sh[i];
#pragma unroll
        for (int o = 16; o > 0; o >>= 1) s += __shfl_down_sync(0xffffffffu, s, o);
        if (tid == 0) sred[0] = s * (1.0f / PDIM);
    }
    __syncthreads();
    const float mu = sred[0];

    float d = score - mu;
    sh[tid] = valid ? d * d : 0.0f;
    __syncthreads();
    if (tid < 32) {
        float s = 0.0f;
        for (int i = tid; i < PDIM; i += 32) s += sh[i];
#pragma unroll
        for (int o = 16; o > 0; o >>= 1) s += __shfl_down_sync(0xffffffffu, s, o);
        if (tid == 0) sred[1] = s * (1.0f / PDIM);
    }
    __syncthreads();
    const float var = sred[1];

    float bin = 0.0f;
    if (valid) {
        float norm = (score - mu) * rsqrtf(var + 1e-5f) * __ldg(&gamma[tid]) + __ldg(&beta[tid]);
        bin = (norm > 0.0f) ? 1.0f : 0.0f;
    }

    sh[tid] = valid ? bin * __ldg(&W[tid]) : 0.0f;
    __syncthreads();
    if (tid < 32) {
        float s = 0.0f;
        for (int i = tid; i < PDIM; i += 32) s += sh[i];
#pragma unroll
        for (int o = 16; o > 0; o >>= 1) s += __shfl_down_sync(0xffffffffu, s, o);
        if (tid == 0) out[b * 2 + 0] = s + __ldg(&lb[0]);
    }
    __syncthreads();
    sh[tid] = valid ? bin * __ldg(&W[PDIM + tid]) : 0.0f;
    __syncthreads();
    if (tid < 32) {
        float s = 0.0f;
        for (int i = tid; i < PDIM; i += 32) s += sh[i];
#pragma unroll
        for (int o = 16; o > 0; o >>= 1) s += __shfl_down_sync(0xffffffffu, s, o);
        if (tid == 0) out[b * 2 + 1] = s + __ldg(&lb[1]);
    }
}

// ---------------------------------------------------------------------------
// launch
// ---------------------------------------------------------------------------
extern "C" void kernel_launch(void* const* d_in, const int* in_sizes, int n_in,
                              void* d_out, int out_size) {
    const int*   docs      = (const int*)  d_in[0];
    const int*   doc_lens  = (const int*)  d_in[1];
    const float* emb       = (const float*)d_in[2];
    const float* diags     = (const float*)d_in[3];
    const float* bias      = (const float*)d_in[4];
    const float* wildcards = (const float*)d_in[5];
    const float* ln_gamma  = (const float*)d_in[6];
    const float* ln_beta   = (const float*)d_in[7];
    const float* linear_w  = (const float*)d_in[8];
    const float* linear_b  = (const float*)d_in[9];
    float*       out       = (float*)d_out;

    (void)in_sizes; (void)n_in; (void)out_size;

    cudaFuncSetAttribute(gemm_mma_kernel,
                         cudaFuncAttributeMaxDynamicSharedMemorySize, GSMEM_TOTAL);

    prepA_kernel<<<SD_BLOCKS + CL_BLOCKS, 256>>>(diags);
    mark_kernel<<<(BDIM * LDIM + 255) / 256, 256>>>(docs, doc_lens);

    dim3 cgrid((VPAD + 31) / 32, (KPAD + 31) / 32 + 1);   // (628, 11)
    prepC_kernel<<<cgrid, dim3(32, 8)>>>(emb);

    dim3 ggrid(VPAD / 64, CPAD / 128);                    // (314, 5)
    gemm_mma_kernel<<<ggrid, 256, GSMEM_TOTAL>>>(bias);

    dim3 sgrid(BDIM, NSC / 2);                            // (64, 8)
    scan_part_kernel<<<sgrid, 160>>>(docs, doc_lens, wildcards);

    scan_final_kernel<<<BDIM, 160>>>(ln_gamma, ln_beta, linear_w, linear_b, out);
}